// round 10
// baseline (speedup 1.0000x reference)
#include <cuda_runtime.h>
#include <cuda_bf16.h>
#include <stdint.h>
#include <stddef.h>

#define Bq  256
#define Lq  196
#define AFq 2048
#define RSq 512
#define AHq 512
#define IEq 512
#define Mq  (Bq * Lq)            // 50176
#define XK  (IEq + AFq + RSq)    // 3072
#define GSEG (Bq * 4 * RSq)      // 524288 (one split-K partial)

// ---------------- device scratch (no allocations allowed) ----------------
__device__ __align__(16) float         g_att_h[Bq * AHq];
__device__ __align__(16) __nv_bfloat16 g_Wctx[AHq * AFq];
__device__ __align__(16) float         g_part[2 * Mq];       // per-nblock partial scores
__device__ __align__(16) float         g_weight[Bq * Lq];
__device__ __align__(16) float         g_x[Bq * XK];          // [xt | att_res | h0] (tf32-rounded)
__device__ __align__(16) float         g_Wg[4 * RSq * XK];    // [Wih | Whh] concat, tf32-rounded
__device__ __align__(16) float         g_gpart[3 * GSEG];     // split-K gate partials

// ---------------- helpers ----------------
__device__ __forceinline__ uint32_t packbf(float lo, float hi) {
    __nv_bfloat162 h = __floats2bfloat162_rn(lo, hi);
    return *reinterpret_cast<uint32_t*>(&h);
}
__device__ __forceinline__ uint32_t f2tf32(float f) {
    uint32_t r; asm("cvt.rna.tf32.f32 %0, %1;" : "=r"(r) : "f"(f)); return r;
}
__device__ __forceinline__ void mma_bf16(float c[4], const uint32_t a[4], const uint32_t b[2]) {
    asm volatile("mma.sync.aligned.m16n8k16.row.col.f32.bf16.bf16.f32 "
        "{%0,%1,%2,%3}, {%4,%5,%6,%7}, {%8,%9}, {%0,%1,%2,%3};"
        : "+f"(c[0]), "+f"(c[1]), "+f"(c[2]), "+f"(c[3])
        : "r"(a[0]), "r"(a[1]), "r"(a[2]), "r"(a[3]), "r"(b[0]), "r"(b[1]));
}
__device__ __forceinline__ void mma_tf32(float c[4], const uint32_t a[4], const uint32_t b[2]) {
    asm volatile("mma.sync.aligned.m16n8k8.row.col.f32.tf32.tf32.f32 "
        "{%0,%1,%2,%3}, {%4,%5,%6,%7}, {%8,%9}, {%0,%1,%2,%3};"
        : "+f"(c[0]), "+f"(c[1]), "+f"(c[2]), "+f"(c[3])
        : "r"(a[0]), "r"(a[1]), "r"(a[2]), "r"(a[3]), "r"(b[0]), "r"(b[1]));
}
__device__ __forceinline__ uint32_t smem_u32(const void* p) {
    return (uint32_t)__cvta_generic_to_shared(p);
}
__device__ __forceinline__ void cp_async16(uint32_t dst, const void* src) {
    asm volatile("cp.async.cg.shared.global [%0], [%1], 16;" :: "r"(dst), "l"(src));
}
__device__ __forceinline__ void cp_commit() {
    asm volatile("cp.async.commit_group;" ::: "memory");
}
__device__ __forceinline__ void cp_wait1() {
    asm volatile("cp.async.wait_group 1;" ::: "memory");
}
__device__ __forceinline__ void ldsm_x4(uint32_t& r0, uint32_t& r1, uint32_t& r2, uint32_t& r3,
                                        uint32_t addr) {
    asm volatile("ldmatrix.sync.aligned.m8n8.x4.shared.b16 {%0,%1,%2,%3}, [%4];"
        : "=r"(r0), "=r"(r1), "=r"(r2), "=r"(r3) : "r"(addr));
}

// ---------------- K0: W_ctx->bf16; xt,h0 -> g_x (tf32-rounded) ----------------
__global__ void k0_prep(const float* __restrict__ Wctx, const float* __restrict__ xt,
                        const float* __restrict__ h0) {
    int i = blockIdx.x * blockDim.x + threadIdx.x;
    if (i < AHq * AFq) g_Wctx[i] = __float2bfloat16(Wctx[i]);
    if (i < Bq * IEq) {
        int b = i >> 9, c = i & 511;
        g_x[(size_t)b * XK + c] = __uint_as_float(f2tf32(xt[i]));
    }
    if (i < Bq * RSq) {
        int b = i >> 9, c = i & 511;
        g_x[(size_t)b * XK + IEq + AFq + c] = __uint_as_float(f2tf32(h0[i]));
    }
}

// ---------------- K0b: g_Wg = [Wih | Whh] tf32-rounded ----------------
__global__ void k0b_wg(const float* __restrict__ Wih, const float* __restrict__ Whh) {
    int i = blockIdx.x * blockDim.x + threadIdx.x;
    if (i >= 4 * RSq * (XK / 4)) return;
    int n = i / (XK / 4), kq = i % (XK / 4);
    float4 v;
    if (kq < 640) v = *(const float4*)(Wih + (size_t)n * 2560 + kq * 4);
    else          v = *(const float4*)(Whh + (size_t)n * 512 + (kq - 640) * 4);
    uint4 o = make_uint4(f2tf32(v.x), f2tf32(v.y), f2tf32(v.z), f2tf32(v.w));
    ((uint4*)g_Wg)[(size_t)n * (XK / 4) + kq] = o;
}

// ---------------- K1: att_h = h0 @ W_h2a^T + b_h2a ----------------
__global__ void k1_atth(const float* __restrict__ h0, const float* __restrict__ W,
                        const float* __restrict__ bias) {
    __shared__ float As[16][16];
    __shared__ float Bs[16][17];
    int tx = threadIdx.x, ty = threadIdx.y;
    int b  = blockIdx.x * 16 + ty;
    int j  = blockIdx.y * 16 + tx;
    float acc = 0.f;
    for (int k0 = 0; k0 < RSq; k0 += 16) {
        As[ty][tx] = h0[b * RSq + k0 + tx];
        Bs[ty][tx] = W[(blockIdx.y * 16 + ty) * RSq + k0 + tx];
        __syncthreads();
        #pragma unroll
        for (int kk = 0; kk < 16; kk++) acc += As[ty][kk] * Bs[tx][kk];
        __syncthreads();
    }
    g_att_h[b * AHq + j] = acc + bias[j];
}

// ---------------- nop: keeps k2 at ncu capture slot ----------------
__global__ void k_nop() {}

// ---------------- K2: fused scores — block 128x256, warp 64x64, 3-stage ----------------
#define BROW 80                  // bf16 tile row stride (64B data + 16 pad)
#define ASTG (128 * BROW)        // 10240
#define BSTG (256 * BROW)        // 20480
#define STG  (ASTG + BSTG)       // 30720 per stage
#define OFF_ADD (3 * STG)                   // 92160
#define OFF_WAL (OFF_ADD + 2 * 256 * 4)     // 94208
#define OFF_RED (OFF_WAL + 256 * 4)         // 95232
#define K2_SMEM (OFF_RED + 128 * 4 * 4)     // 97280
#define NKT2 (AFq / 32)          // 64

__global__ void __launch_bounds__(256, 1)
k2_scores(const float* __restrict__ att, const float* __restrict__ bctx,
          const float* __restrict__ Wal) {
    extern __shared__ __align__(16) char sm[];
    uint32_t smb = smem_u32(sm);
    float* s_add = (float*)(sm + OFF_ADD);   // [2][256]
    float* s_wal = (float*)(sm + OFF_WAL);   // [256]
    float* s_red = (float*)(sm + OFF_RED);   // [128][4]

    int tid = threadIdx.x;
    int warp = tid >> 5, lane = tid & 31;
    int g = lane >> 2, t = lane & 3;
    int wm = warp >> 2, wn = warp & 3;        // 2m x 4n, warp tile 64x64
    int nb    = blockIdx.x;                    // 0..1
    int mbase = blockIdx.y * 128;
    int nbase = nb * 256;
    int b0 = mbase / Lq;

    {   // epilogue constants: 2x256 adds + 256 wal
        int nc = tid;                          // 0..255
        s_wal[nc] = Wal[nbase + nc];
        #pragma unroll
        for (int j = 0; j < 2; j++) {
            int bb = b0 + j; if (bb >= Bq) bb = Bq - 1;
            s_add[j * 256 + nc] = bctx[nbase + nc] + g_att_h[(size_t)bb * AHq + nbase + nc];
        }
    }

    float acc[4][8][4];
    #pragma unroll
    for (int a = 0; a < 4; a++)
        #pragma unroll
        for (int b = 0; b < 8; b++)
            #pragma unroll
            for (int c = 0; c < 4; c++) acc[a][b][c] = 0.f;

    // staging: A 128 rows x 32 cols f32->bf16 (4 LDG.128 + 4 STS.64 per thread)
    const float* aP[4];  uint32_t aOff[4];
    #pragma unroll
    for (int q = 0; q < 4; q++) {
        int idx = q * 256 + tid;
        int row = idx >> 3, seg = idx & 7;
        aP[q]   = att + (size_t)(mbase + row) * AFq + seg * 4;
        aOff[q] = row * BROW + seg * 8;
    }
    // B 256 rows x 32 cols bf16 (4 cp.async16 per thread)
    const __nv_bfloat16* bP[4]; uint32_t bOff[4];
    #pragma unroll
    for (int q = 0; q < 4; q++) {
        int idx = q * 256 + tid;
        int row = idx >> 2, c = idx & 3;
        bP[q]   = g_Wctx + (size_t)(nbase + row) * AFq + c * 8;
        bOff[q] = ASTG + row * BROW + c * 16;
    }

    uint2 regA[4];
    auto ldgA = [&](int kt) {
        int k0 = kt * 32;
        #pragma unroll
        for (int q = 0; q < 4; q++) {
            float4 v = *(const float4*)(aP[q] + k0);
            regA[q] = make_uint2(packbf(v.x, v.y), packbf(v.z, v.w));
        }
    };
    auto stsA = [&](int s) {
        uint32_t base = smb + s * STG;
        #pragma unroll
        for (int q = 0; q < 4; q++)
            asm volatile("st.shared.v2.b32 [%0], {%1, %2};"
                :: "r"(base + aOff[q]), "r"(regA[q].x), "r"(regA[q].y) : "memory");
    };
    auto cpB = [&](int kt, int s) {
        int k0 = kt * 32;
        uint32_t base = smb + s * STG;
        #pragma unroll
        for (int q = 0; q < 4; q++)
            cp_async16(base + bOff[q], bP[q] + k0);
    };

    // ldmatrix fragment addresses
    uint32_t a_off = (uint32_t)(wm * 64 + (lane & 15)) * BROW + ((lane & 16) ? 16 : 0);
    uint32_t b_off = ASTG + (uint32_t)(wn * 64 + ((lane >> 4) & 1) * 8 + (lane & 7)) * BROW +
                     ((lane >> 3) & 1) * 16;

    ldgA(0);
    cpB(0, 0); cp_commit();
    cpB(1, 1); cp_commit();

    for (int kt = 0; kt < NKT2; kt++) {
        int s = kt % 3;
        stsA(s);
        cp_wait1();
        __syncthreads();
        if (kt < NKT2 - 1) ldgA(kt + 1);
        if (kt < NKT2 - 2) cpB(kt + 2, (kt + 2) % 3);
        cp_commit();

        uint32_t aBase = smb + s * STG + a_off;
        uint32_t bBase = smb + s * STG + b_off;
        #pragma unroll
        for (int k16 = 0; k16 < 2; k16++) {
            uint32_t bfr[8][2];
            #pragma unroll
            for (int p = 0; p < 4; p++)
                ldsm_x4(bfr[2 * p][0], bfr[2 * p][1], bfr[2 * p + 1][0], bfr[2 * p + 1][1],
                        bBase + (uint32_t)p * 16 * BROW + k16 * 32);
            #pragma unroll
            for (int mf = 0; mf < 4; mf++) {
                uint32_t afr[4];
                ldsm_x4(afr[0], afr[1], afr[2], afr[3],
                        aBase + (uint32_t)mf * 16 * BROW + k16 * 32);
                #pragma unroll
                for (int nf = 0; nf < 8; nf++)
                    mma_bf16(acc[mf][nf], afr, bfr[nf]);
            }
        }
    }

    // epilogue: partial score over this block's 256 columns
    float rs[4][2];
    #pragma unroll
    for (int mf = 0; mf < 4; mf++) {
        #pragma unroll
        for (int hh = 0; hh < 2; hh++) {
            int row_l = wm * 64 + mf * 16 + hh * 8 + g;
            int m = mbase + row_l;
            int jb = (m / Lq) - b0; if (jb > 1) jb = 1;
            const float* addp = s_add + jb * 256;
            float s = 0.f;
            #pragma unroll
            for (int nf = 0; nf < 8; nf++) {
                #pragma unroll
                for (int ci = 0; ci < 2; ci++) {
                    int nc = wn * 64 + nf * 8 + 2 * t + ci;
                    float v = acc[mf][nf][hh * 2 + ci] + addp[nc];
                    s += s_wal[nc] * tanhf(v);
                }
            }
            rs[mf][hh] = s;
        }
    }
    #pragma unroll
    for (int off = 1; off < 4; off <<= 1)
        #pragma unroll
        for (int mf = 0; mf < 4; mf++)
            #pragma unroll
            for (int hh = 0; hh < 2; hh++)
                rs[mf][hh] += __shfl_xor_sync(0xffffffffu, rs[mf][hh], off);
    __syncthreads();
    if (t == 0) {
        #pragma unroll
        for (int mf = 0; mf < 4; mf++)
            #pragma unroll
            for (int hh = 0; hh < 2; hh++)
                s_red[(wm * 64 + mf * 16 + hh * 8 + g) * 4 + wn] = rs[mf][hh];
    }
    __syncthreads();
    if (tid < 128) {
        float s = s_red[tid * 4] + s_red[tid * 4 + 1] + s_red[tid * 4 + 2] + s_red[tid * 4 + 3];
        g_part[(size_t)nb * Mq + mbase + tid] = s;
    }
}

// ---------------- K3: sum 2 partials + softmax over L=196 ----------------
__global__ void k3_softmax(const float* __restrict__ bal) {
    int b = blockIdx.x;
    int tid = threadIdx.x;
    __shared__ float sh[256];
    float v = -1e30f;
    if (tid < Lq) {
        int m = b * Lq + tid;
        v = g_part[m] + g_part[Mq + m] + bal[0];
    }
    sh[tid] = v; __syncthreads();
    for (int s = 128; s > 0; s >>= 1) {
        if (tid < s) sh[tid] = fmaxf(sh[tid], sh[tid + s]);
        __syncthreads();
    }
    float mx = sh[0]; __syncthreads();
    float e = (tid < Lq) ? __expf(v - mx) : 0.f;
    sh[tid] = e; __syncthreads();
    for (int s = 128; s > 0; s >>= 1) {
        if (tid < s) sh[tid] += sh[tid + s];
        __syncthreads();
    }
    float inv = 1.f / sh[0];
    if (tid < Lq) g_weight[b * Lq + tid] = e * inv;
}

// ---------------- K4: att_res = weight @ att_feats (tf32-rounded into g_x) ----------------
__global__ void k4_attres(const float* __restrict__ att) {
    int b  = blockIdx.y;
    int a0 = blockIdx.x * 1024 + threadIdx.x * 4;
    __shared__ float w[Lq];
    for (int i = threadIdx.x; i < Lq; i += blockDim.x) w[i] = g_weight[b * Lq + i];
    __syncthreads();
    float4 acc = make_float4(0.f, 0.f, 0.f, 0.f);
    const float* base = att + (size_t)b * Lq * AFq + a0;
    #pragma unroll 4
    for (int l = 0; l < Lq; l++) {
        float4 v = *(const float4*)(base + (size_t)l * AFq);
        float wl = w[l];
        acc.x += wl * v.x; acc.y += wl * v.y; acc.z += wl * v.z; acc.w += wl * v.w;
    }
    acc.x = __uint_as_float(f2tf32(acc.x));
    acc.y = __uint_as_float(f2tf32(acc.y));
    acc.z = __uint_as_float(f2tf32(acc.z));
    acc.w = __uint_as_float(f2tf32(acc.w));
    *(float4*)(g_x + (size_t)b * XK + IEq + a0) = acc;
}

// ---------------- K5: gate GEMM, tf32, cp.async tiled, split-K=3 ----------------
#define R5 144
#define S5 (128 * R5)
#define K5_SMEM (6 * S5)
__global__ void __launch_bounds__(256, 1)
k5_gates() {
    extern __shared__ __align__(16) char sm5[];
    uint32_t smb = smem_u32(sm5);
    int tid = threadIdx.x;
    int warp = tid >> 5, lane = tid & 31;
    int g = lane >> 2, t = lane & 3;
    int wm = warp >> 2, wn = warp & 3;
    int mbase = blockIdx.x * 128;
    int nbase = blockIdx.y * 128;
    int kb    = blockIdx.z * 1024;

    float acc[4][4][4];
    #pragma unroll
    for (int a = 0; a < 4; a++)
        #pragma unroll
        for (int b = 0; b < 4; b++)
            #pragma unroll
            for (int c = 0; c < 4; c++) acc[a][b][c] = 0.f;

    const float* aP[4]; const float* bP[4]; uint32_t tOff[4];
    #pragma unroll
    for (int q = 0; q < 4; q++) {
        int idx = q * 256 + tid;
        int row = idx >> 3, seg = idx & 7;
        aP[q] = g_x  + (size_t)(mbase + row) * XK + kb + seg * 4;
        bP[q] = g_Wg + (size_t)(nbase + row) * XK + kb + seg * 4;
        tOff[q] = row * R5 + seg * 16;
    }
    auto issue = [&](int kt, int s) {
        int k0 = kt * 32;
        uint32_t aD = smb + s * S5;
        uint32_t bD = smb + 3 * S5 + s * S5;
        #pragma unroll
        for (int q = 0; q < 4; q++) {
            cp_async16(aD + tOff[q], aP[q] + k0);
            cp_async16(bD + tOff[q], bP[q] + k0);
        }
    };

    issue(0, 0); cp_commit();
    issue(1, 1); cp_commit();

    uint32_t aFr = (uint32_t)(wm * 64 + g) * R5 + t * 4;
    uint32_t bFr = (uint32_t)(wn * 32 + g) * R5 + t * 4;

    for (int kt = 0; kt < 32; kt++) {
        int s = kt % 3;
        cp_wait1();
        __syncthreads();
        if (kt < 30) issue(kt + 2, (kt + 2) % 3);
        cp_commit();

        const char* aB = sm5 + s * S5;
        const char* bB = sm5 + 3 * S5 + s * S5;
        #pragma unroll
        for (int ks = 0; ks < 4; ks++) {
            uint32_t kc = ks * 32;
            uint32_t bfr[4][2];
            #pragma unroll
            for (int nf = 0; nf < 4; nf++) {
                bfr[nf][0] = *(const uint32_t*)(bB + bFr + nf * 8 * R5 + kc);
                bfr[nf][1] = *(const uint32_t*)(bB + bFr + nf * 8 * R5 + kc + 16);
            }
            #pragma unroll
            for (int mf = 0; mf < 4; mf++) {
                uint32_t afr[4];
                afr[0] = *(const uint32_t*)(aB + aFr + mf * 16 * R5 + kc);
                afr[1] = *(const uint32_t*)(aB + aFr + (mf * 16 + 8) * R5 + kc);
                afr[2] = *(const uint32_t*)(aB + aFr + mf * 16 * R5 + kc + 16);
                afr[3] = *(const uint32_t*)(aB + aFr + (mf * 16 + 8) * R5 + kc + 16);
                #pragma unroll
                for (int nf = 0; nf < 4; nf++)
                    mma_tf32(acc[mf][nf], afr, bfr[nf]);
            }
        }
    }

    float* outp = g_gpart + (size_t)blockIdx.z * GSEG;
    #pragma unroll
    for (int mf = 0; mf < 4; mf++)
        #pragma unroll
        for (int nf = 0; nf < 4; nf++)
            #pragma unroll
            for (int idx = 0; idx < 4; idx++) {
                int hh = idx >> 1, ci = idx & 1;
                int row = mbase + wm * 64 + mf * 16 + hh * 8 + g;
                int col = nbase + wn * 32 + nf * 8 + 2 * t + ci;
                outp[(size_t)row * 2048 + col] = acc[mf][nf][idx];
            }
}

// ---------------- K6: sum split-K partials + LSTM pointwise + output ----------------
__global__ void k6_lstm(const float* __restrict__ c0, float* __restrict__ out, int out_size) {
    int i = blockIdx.x * blockDim.x + threadIdx.x;
    if (i >= Bq * RSq) return;
    int b = i >> 9, r = i & 511;
    size_t base = (size_t)b * 2048;
    auto gv = [&](int col) {
        size_t idx = base + col;
        return g_gpart[idx] + g_gpart[GSEG + idx] + g_gpart[2 * (size_t)GSEG + idx];
    };
    float gi = 1.f / (1.f + __expf(-gv(r)));
    float gf = 1.f / (1.f + __expf(-gv(512 + r)));
    float gg = tanhf(gv(1024 + r));
    float go = 1.f / (1.f + __expf(-gv(1536 + r)));
    float c = gf * c0[i] + gi * gg;
    float h = go * tanhf(c);
    const int N = Bq * RSq;
    out[i] = h;
    if (out_size >= 3 * N) { out[N + i] = h; out[2 * N + i] = c; }
    else if (out_size >= 2 * N) { out[N + i] = c; }
}

// ---------------- launch ----------------
extern "C" void kernel_launch(void* const* d_in, const int* in_sizes, int n_in,
                              void* d_out, int out_size) {
    const float* xt   = (const float*)d_in[0];
    const float* att  = (const float*)d_in[2];
    const float* h0   = (const float*)d_in[3];
    const float* c0   = (const float*)d_in[4];
    const float* Wctx = (const float*)d_in[5];
    const float* bctx = (const float*)d_in[6];
    const float* Wh2a = (const float*)d_in[7];
    const float* bh2a = (const float*)d_in[8];
    const float* Wal  = (const float*)d_in[9];
    const float* bal  = (const float*)d_in[10];
    const float* Wih  = (const float*)d_in[11];
    const float* Whh  = (const float*)d_in[12];
    float* out = (float*)d_out;

    static int attr_set = 0;
    if (!attr_set) {
        cudaFuncSetAttribute(k2_scores, cudaFuncAttributeMaxDynamicSharedMemorySize, K2_SMEM);
        cudaFuncSetAttribute(k5_gates,  cudaFuncAttributeMaxDynamicSharedMemorySize, K5_SMEM);
        attr_set = 1;
    }

    k0_prep<<<4096, 256>>>(Wctx, xt, h0);
    k1_atth<<<dim3(16, 32), dim3(16, 16)>>>(h0, Wh2a, bh2a);
    k_nop<<<1, 32>>>();
    k2_scores<<<dim3(2, Mq / 128), 256, K2_SMEM>>>(att, bctx, Wal);   // capture slot 3
    k3_softmax<<<Bq, 256>>>(bal);
    k0b_wg<<<6144, 256>>>(Wih, Whh);
    k4_attres<<<dim3(2, Bq), 256>>>(att);
    k5_gates<<<dim3(2, 16, 3), 256, K5_SMEM>>>();
    k6_lstm<<<(Bq * RSq + 255) / 256, 256>>>(c0, out, out_size);
}

// round 12
// speedup vs baseline: 1.1402x; 1.1402x over previous
#include <cuda_runtime.h>
#include <cuda_bf16.h>
#include <stdint.h>
#include <stddef.h>

#define Bq  256
#define Lq  196
#define AFq 2048
#define RSq 512
#define AHq 512
#define IEq 512
#define Mq  (Bq * Lq)            // 50176
#define XK  (IEq + AFq + RSq)    // 3072
#define GSEG (Bq * 4 * RSq)      // 524288 (one split-K partial)

// ---------------- device scratch (no allocations allowed) ----------------
__device__ __align__(16) float         g_att_h[Bq * AHq];
__device__ __align__(16) __nv_bfloat16 g_Wctx[AHq * AFq];
__device__ __align__(16) float         g_part[4 * Mq];       // per-nblock partial scores
__device__ __align__(16) float         g_weight[Bq * Lq];
__device__ __align__(16) float         g_x[Bq * XK];          // [xt | att_res | h0] (tf32-rounded)
__device__ __align__(16) float         g_Wg[4 * RSq * XK];    // [Wih | Whh] concat, tf32-rounded
__device__ __align__(16) float         g_gpart[3 * GSEG];     // split-K gate partials

// ---------------- helpers ----------------
__device__ __forceinline__ uint32_t packbf(float lo, float hi) {
    __nv_bfloat162 h = __floats2bfloat162_rn(lo, hi);
    return *reinterpret_cast<uint32_t*>(&h);
}
__device__ __forceinline__ uint32_t f2tf32(float f) {
    uint32_t r; asm("cvt.rna.tf32.f32 %0, %1;" : "=r"(r) : "f"(f)); return r;
}
__device__ __forceinline__ void mma_bf16(float c[4], const uint32_t a[4], const uint32_t b[2]) {
    asm volatile("mma.sync.aligned.m16n8k16.row.col.f32.bf16.bf16.f32 "
        "{%0,%1,%2,%3}, {%4,%5,%6,%7}, {%8,%9}, {%0,%1,%2,%3};"
        : "+f"(c[0]), "+f"(c[1]), "+f"(c[2]), "+f"(c[3])
        : "r"(a[0]), "r"(a[1]), "r"(a[2]), "r"(a[3]), "r"(b[0]), "r"(b[1]));
}
__device__ __forceinline__ void mma_tf32(float c[4], const uint32_t a[4], const uint32_t b[2]) {
    asm volatile("mma.sync.aligned.m16n8k8.row.col.f32.tf32.tf32.f32 "
        "{%0,%1,%2,%3}, {%4,%5,%6,%7}, {%8,%9}, {%0,%1,%2,%3};"
        : "+f"(c[0]), "+f"(c[1]), "+f"(c[2]), "+f"(c[3])
        : "r"(a[0]), "r"(a[1]), "r"(a[2]), "r"(a[3]), "r"(b[0]), "r"(b[1]));
}
__device__ __forceinline__ uint32_t smem_u32(const void* p) {
    return (uint32_t)__cvta_generic_to_shared(p);
}
__device__ __forceinline__ void cp_async16(uint32_t dst, const void* src) {
    asm volatile("cp.async.cg.shared.global [%0], [%1], 16;" :: "r"(dst), "l"(src));
}
__device__ __forceinline__ void cp_commit() {
    asm volatile("cp.async.commit_group;" ::: "memory");
}
__device__ __forceinline__ void cp_wait1() {
    asm volatile("cp.async.wait_group 1;" ::: "memory");
}
__device__ __forceinline__ void ldsm_x4(uint32_t& r0, uint32_t& r1, uint32_t& r2, uint32_t& r3,
                                        uint32_t addr) {
    asm volatile("ldmatrix.sync.aligned.m8n8.x4.shared.b16 {%0,%1,%2,%3}, [%4];"
        : "=r"(r0), "=r"(r1), "=r"(r2), "=r"(r3) : "r"(addr));
}

// ---------------- K0: W_ctx->bf16; xt,h0 -> g_x (tf32-rounded) ----------------
__global__ void k0_prep(const float* __restrict__ Wctx, const float* __restrict__ xt,
                        const float* __restrict__ h0) {
    int i = blockIdx.x * blockDim.x + threadIdx.x;
    if (i < AHq * AFq) g_Wctx[i] = __float2bfloat16(Wctx[i]);
    if (i < Bq * IEq) {
        int b = i >> 9, c = i & 511;
        g_x[(size_t)b * XK + c] = __uint_as_float(f2tf32(xt[i]));
    }
    if (i < Bq * RSq) {
        int b = i >> 9, c = i & 511;
        g_x[(size_t)b * XK + IEq + AFq + c] = __uint_as_float(f2tf32(h0[i]));
    }
}

// ---------------- K0b: g_Wg = [Wih | Whh] tf32-rounded ----------------
__global__ void k0b_wg(const float* __restrict__ Wih, const float* __restrict__ Whh) {
    int i = blockIdx.x * blockDim.x + threadIdx.x;
    if (i >= 4 * RSq * (XK / 4)) return;
    int n = i / (XK / 4), kq = i % (XK / 4);
    float4 v;
    if (kq < 640) v = *(const float4*)(Wih + (size_t)n * 2560 + kq * 4);
    else          v = *(const float4*)(Whh + (size_t)n * 512 + (kq - 640) * 4);
    uint4 o = make_uint4(f2tf32(v.x), f2tf32(v.y), f2tf32(v.z), f2tf32(v.w));
    ((uint4*)g_Wg)[(size_t)n * (XK / 4) + kq] = o;
}

// ---------------- K1: att_h = h0 @ W_h2a^T + b_h2a ----------------
__global__ void k1_atth(const float* __restrict__ h0, const float* __restrict__ W,
                        const float* __restrict__ bias) {
    __shared__ float As[16][16];
    __shared__ float Bs[16][17];
    int tx = threadIdx.x, ty = threadIdx.y;
    int b  = blockIdx.x * 16 + ty;
    int j  = blockIdx.y * 16 + tx;
    float acc = 0.f;
    for (int k0 = 0; k0 < RSq; k0 += 16) {
        As[ty][tx] = h0[b * RSq + k0 + tx];
        Bs[ty][tx] = W[(blockIdx.y * 16 + ty) * RSq + k0 + tx];
        __syncthreads();
        #pragma unroll
        for (int kk = 0; kk < 16; kk++) acc += As[ty][kk] * Bs[tx][kk];
        __syncthreads();
    }
    g_att_h[b * AHq + j] = acc + bias[j];
}

// ---------------- nop: keeps k2 at ncu capture slot ----------------
__global__ void k_nop() {}

// ---------------- K2: fused scores — R8-proven 3-stage cp.async bf16 mma.sync ----------------
// Grid (4, 392): nb fastest (A L2 reuse). Block 256 = 8 warps (2m x 4n). Tile 128x128xk32.
#define AROW 160                 // f32 A tile row stride bytes
#define A_STG (128 * AROW)       // 20480
#define BROW 80                  // bf16 B tile row stride
#define B_STG (128 * BROW)       // 10240
#define OFF_B   (3 * A_STG)                 // 61440
#define OFF_ADD (OFF_B + 3 * B_STG)         // 92160
#define OFF_WAL (OFF_ADD + 2 * 128 * 4)     // 93184
#define OFF_RED (OFF_WAL + 128 * 4)         // 93696
#define K2_SMEM (OFF_RED + 128 * 4 * 4)     // 95744
#define NKT2 (AFq / 32)          // 64

__global__ void __launch_bounds__(256, 2)
k2_scores(const float* __restrict__ att, const float* __restrict__ bctx,
          const float* __restrict__ Wal) {
    extern __shared__ __align__(16) char sm[];
    uint32_t smb = smem_u32(sm);
    float* s_add = (float*)(sm + OFF_ADD);   // [2][128]
    float* s_wal = (float*)(sm + OFF_WAL);   // [128]
    float* s_red = (float*)(sm + OFF_RED);   // [128][4]

    int tid = threadIdx.x;
    int warp = tid >> 5, lane = tid & 31;
    int g = lane >> 2, t = lane & 3;
    int wm = warp >> 2, wn = warp & 3;          // 2 x 4
    int nb    = blockIdx.x;                      // 0..3 (fast dim -> L2 A sharing)
    int mbase = blockIdx.y * 128;
    int nbase = nb * 128;
    int b0 = mbase / Lq;

    {
        int j = tid >> 7, nc = tid & 127;
        int bb = b0 + j; if (bb >= Bq) bb = Bq - 1;
        s_add[j * 128 + nc] = bctx[nbase + nc] + g_att_h[(size_t)bb * AHq + nbase + nc];
        if (tid < 128) s_wal[tid] = Wal[nbase + tid];
    }

    float acc[4][4][4];
    #pragma unroll
    for (int a = 0; a < 4; a++)
        #pragma unroll
        for (int b = 0; b < 4; b++)
            #pragma unroll
            for (int c = 0; c < 4; c++) acc[a][b][c] = 0.f;

    // stage loaders: A fp32 (4 x 16B per thread), B bf16 (2 x 16B per thread)
    auto issue_stage = [&](int kt, int s) {
        int k0 = kt * 32;
        uint32_t aDst = smb + s * A_STG;
        #pragma unroll
        for (int q = 0; q < 4; q++) {
            int idx = q * 256 + tid;
            int row = idx >> 3, seg = idx & 7;
            cp_async16(aDst + row * AROW + seg * 16,
                       att + (size_t)(mbase + row) * AFq + k0 + seg * 4);
        }
        uint32_t bDst = smb + OFF_B + s * B_STG;
        #pragma unroll
        for (int q = 0; q < 2; q++) {
            int idx = q * 256 + tid;
            int row = idx >> 2, c = idx & 3;
            cp_async16(bDst + row * BROW + c * 16,
                       g_Wctx + (size_t)(nbase + row) * AFq + k0 + c * 8);
        }
    };

    // B ldmatrix address (R7-proven mapping)
    uint32_t b_off = (uint32_t)(wn * 32 + ((lane >> 4) & 1) * 8 + (lane & 7)) * BROW +
                     ((lane >> 3) & 1) * 16;
    // A LDS base: row = wm*64 + mf*16 + g, col = k16*16 + 2t (f32)
    uint32_t a_off = (uint32_t)(wm * 64 + g) * AROW + t * 8;

    // prologue: stages 0,1
    issue_stage(0, 0); cp_commit();
    issue_stage(1, 1); cp_commit();

    for (int kt = 0; kt < NKT2; kt++) {
        int s = kt % 3;
        cp_wait1();
        __syncthreads();
        if (kt + 2 < NKT2) issue_stage(kt + 2, (kt + 2) % 3);
        cp_commit();

        uint32_t aBase = smb + s * A_STG + a_off;
        uint32_t bBase = smb + OFF_B + s * B_STG + b_off;
        #pragma unroll
        for (int k16 = 0; k16 < 2; k16++) {
            uint32_t bfr[4][2];
            ldsm_x4(bfr[0][0], bfr[0][1], bfr[1][0], bfr[1][1], bBase + k16 * 32);
            ldsm_x4(bfr[2][0], bfr[2][1], bfr[3][0], bfr[3][1], bBase + 16 * BROW + k16 * 32);
            #pragma unroll
            for (int mf = 0; mf < 4; mf++) {
                uint32_t ab = aBase + (uint32_t)mf * 16 * AROW + k16 * 64;
                float2 v00 = *(const float2*)(sm + (ab - smb));
                float2 v10 = *(const float2*)(sm + (ab - smb) + 8 * AROW);
                float2 v01 = *(const float2*)(sm + (ab - smb) + 32);
                float2 v11 = *(const float2*)(sm + (ab - smb) + 8 * AROW + 32);
                uint32_t afr[4] = { packbf(v00.x, v00.y), packbf(v10.x, v10.y),
                                    packbf(v01.x, v01.y), packbf(v11.x, v11.y) };
                #pragma unroll
                for (int nf = 0; nf < 4; nf++)
                    mma_bf16(acc[mf][nf], afr, bfr[nf]);
            }
        }
        __syncthreads();
    }

    // epilogue: partial score over this block's 128 columns
    float rs[4][2];
    #pragma unroll
    for (int mf = 0; mf < 4; mf++) {
        #pragma unroll
        for (int hh = 0; hh < 2; hh++) {
            int row_l = wm * 64 + mf * 16 + hh * 8 + g;
            int m = mbase + row_l;
            int jb = (m / Lq) - b0; if (jb > 1) jb = 1;
            const float* addp = s_add + jb * 128;
            float s = 0.f;
            #pragma unroll
            for (int nf = 0; nf < 4; nf++) {
                #pragma unroll
                for (int ci = 0; ci < 2; ci++) {
                    int nc = wn * 32 + nf * 8 + 2 * t + ci;
                    float v = acc[mf][nf][hh * 2 + ci] + addp[nc];
                    s += s_wal[nc] * tanhf(v);
                }
            }
            rs[mf][hh] = s;
        }
    }
    #pragma unroll
    for (int off = 1; off < 4; off <<= 1)
        #pragma unroll
        for (int mf = 0; mf < 4; mf++)
            #pragma unroll
            for (int hh = 0; hh < 2; hh++)
                rs[mf][hh] += __shfl_xor_sync(0xffffffffu, rs[mf][hh], off);
    if (t == 0) {
        #pragma unroll
        for (int mf = 0; mf < 4; mf++)
            #pragma unroll
            for (int hh = 0; hh < 2; hh++)
                s_red[(wm * 64 + mf * 16 + hh * 8 + g) * 4 + wn] = rs[mf][hh];
    }
    __syncthreads();
    if (tid < 128) {
        float s = s_red[tid * 4] + s_red[tid * 4 + 1] + s_red[tid * 4 + 2] + s_red[tid * 4 + 3];
        g_part[(size_t)nb * Mq + mbase + tid] = s;
    }
}

// ---------------- K3: sum 4 partials + softmax over L=196 ----------------
__global__ void k3_softmax(const float* __restrict__ bal) {
    int b = blockIdx.x;
    int tid = threadIdx.x;
    __shared__ float sh[256];
    float v = -1e30f;
    if (tid < Lq) {
        int m = b * Lq + tid;
        v = g_part[m] + g_part[Mq + m] + g_part[2 * Mq + m] + g_part[3 * Mq + m] + bal[0];
    }
    sh[tid] = v; __syncthreads();
    for (int s = 128; s > 0; s >>= 1) {
        if (tid < s) sh[tid] = fmaxf(sh[tid], sh[tid + s]);
        __syncthreads();
    }
    float mx = sh[0]; __syncthreads();
    float e = (tid < Lq) ? __expf(v - mx) : 0.f;
    sh[tid] = e; __syncthreads();
    for (int s = 128; s > 0; s >>= 1) {
        if (tid < s) sh[tid] += sh[tid + s];
        __syncthreads();
    }
    float inv = 1.f / sh[0];
    if (tid < Lq) g_weight[b * Lq + tid] = e * inv;
}

// ---------------- K4: att_res = weight @ att_feats (tf32-rounded into g_x) ----------------
__global__ void k4_attres(const float* __restrict__ att) {
    int b  = blockIdx.y;
    int a0 = blockIdx.x * 1024 + threadIdx.x * 4;
    __shared__ float w[Lq];
    for (int i = threadIdx.x; i < Lq; i += blockDim.x) w[i] = g_weight[b * Lq + i];
    __syncthreads();
    float4 acc = make_float4(0.f, 0.f, 0.f, 0.f);
    const float* base = att + (size_t)b * Lq * AFq + a0;
    #pragma unroll 4
    for (int l = 0; l < Lq; l++) {
        float4 v = *(const float4*)(base + (size_t)l * AFq);
        float wl = w[l];
        acc.x += wl * v.x; acc.y += wl * v.y; acc.z += wl * v.z; acc.w += wl * v.w;
    }
    acc.x = __uint_as_float(f2tf32(acc.x));
    acc.y = __uint_as_float(f2tf32(acc.y));
    acc.z = __uint_as_float(f2tf32(acc.z));
    acc.w = __uint_as_float(f2tf32(acc.w));
    *(float4*)(g_x + (size_t)b * XK + IEq + a0) = acc;
}

// ---------------- K5: gate GEMM, tf32, cp.async tiled, split-K=3 ----------------
#define R5 144
#define S5 (128 * R5)
#define K5_SMEM (6 * S5)
__global__ void __launch_bounds__(256, 1)
k5_gates() {
    extern __shared__ __align__(16) char sm5[];
    uint32_t smb = smem_u32(sm5);
    int tid = threadIdx.x;
    int warp = tid >> 5, lane = tid & 31;
    int g = lane >> 2, t = lane & 3;
    int wm = warp >> 2, wn = warp & 3;
    int mbase = blockIdx.x * 128;
    int nbase = blockIdx.y * 128;
    int kb    = blockIdx.z * 1024;

    float acc[4][4][4];
    #pragma unroll
    for (int a = 0; a < 4; a++)
        #pragma unroll
        for (int b = 0; b < 4; b++)
            #pragma unroll
            for (int c = 0; c < 4; c++) acc[a][b][c] = 0.f;

    const float* aP[4]; const float* bP[4]; uint32_t tOff[4];
    #pragma unroll
    for (int q = 0; q < 4; q++) {
        int idx = q * 256 + tid;
        int row = idx >> 3, seg = idx & 7;
        aP[q] = g_x  + (size_t)(mbase + row) * XK + kb + seg * 4;
        bP[q] = g_Wg + (size_t)(nbase + row) * XK + kb + seg * 4;
        tOff[q] = row * R5 + seg * 16;
    }
    auto issue = [&](int kt, int s) {
        int k0 = kt * 32;
        uint32_t aD = smb + s * S5;
        uint32_t bD = smb + 3 * S5 + s * S5;
        #pragma unroll
        for (int q = 0; q < 4; q++) {
            cp_async16(aD + tOff[q], aP[q] + k0);
            cp_async16(bD + tOff[q], bP[q] + k0);
        }
    };

    issue(0, 0); cp_commit();
    issue(1, 1); cp_commit();

    uint32_t aFr = (uint32_t)(wm * 64 + g) * R5 + t * 4;
    uint32_t bFr = (uint32_t)(wn * 32 + g) * R5 + t * 4;

    for (int kt = 0; kt < 32; kt++) {
        int s = kt % 3;
        cp_wait1();
        __syncthreads();
        if (kt < 30) issue(kt + 2, (kt + 2) % 3);
        cp_commit();

        const char* aB = sm5 + s * S5;
        const char* bB = sm5 + 3 * S5 + s * S5;
        #pragma unroll
        for (int ks = 0; ks < 4; ks++) {
            uint32_t kc = ks * 32;
            uint32_t bfr[4][2];
            #pragma unroll
            for (int nf = 0; nf < 4; nf++) {
                bfr[nf][0] = *(const uint32_t*)(bB + bFr + nf * 8 * R5 + kc);
                bfr[nf][1] = *(const uint32_t*)(bB + bFr + nf * 8 * R5 + kc + 16);
            }
            #pragma unroll
            for (int mf = 0; mf < 4; mf++) {
                uint32_t afr[4];
                afr[0] = *(const uint32_t*)(aB + aFr + mf * 16 * R5 + kc);
                afr[1] = *(const uint32_t*)(aB + aFr + (mf * 16 + 8) * R5 + kc);
                afr[2] = *(const uint32_t*)(aB + aFr + mf * 16 * R5 + kc + 16);
                afr[3] = *(const uint32_t*)(aB + aFr + (mf * 16 + 8) * R5 + kc + 16);
                #pragma unroll
                for (int nf = 0; nf < 4; nf++)
                    mma_tf32(acc[mf][nf], afr, bfr[nf]);
            }
        }
    }

    float* outp = g_gpart + (size_t)blockIdx.z * GSEG;
    #pragma unroll
    for (int mf = 0; mf < 4; mf++)
        #pragma unroll
        for (int nf = 0; nf < 4; nf++)
            #pragma unroll
            for (int idx = 0; idx < 4; idx++) {
                int hh = idx >> 1, ci = idx & 1;
                int row = mbase + wm * 64 + mf * 16 + hh * 8 + g;
                int col = nbase + wn * 32 + nf * 8 + 2 * t + ci;
                outp[(size_t)row * 2048 + col] = acc[mf][nf][idx];
            }
}

// ---------------- K6: sum split-K partials + LSTM pointwise + output ----------------
__global__ void k6_lstm(const float* __restrict__ c0, float* __restrict__ out, int out_size) {
    int i = blockIdx.x * blockDim.x + threadIdx.x;
    if (i >= Bq * RSq) return;
    int b = i >> 9, r = i & 511;
    size_t base = (size_t)b * 2048;
    auto gv = [&](int col) {
        size_t idx = base + col;
        return g_gpart[idx] + g_gpart[GSEG + idx] + g_gpart[2 * (size_t)GSEG + idx];
    };
    float gi = 1.f / (1.f + __expf(-gv(r)));
    float gf = 1.f / (1.f + __expf(-gv(512 + r)));
    float gg = tanhf(gv(1024 + r));
    float go = 1.f / (1.f + __expf(-gv(1536 + r)));
    float c = gf * c0[i] + gi * gg;
    float h = go * tanhf(c);
    const int N = Bq * RSq;
    out[i] = h;
    if (out_size >= 3 * N) { out[N + i] = h; out[2 * N + i] = c; }
    else if (out_size >= 2 * N) { out[N + i] = c; }
}

// ---------------- launch ----------------
extern "C" void kernel_launch(void* const* d_in, const int* in_sizes, int n_in,
                              void* d_out, int out_size) {
    const float* xt   = (const float*)d_in[0];
    const float* att  = (const float*)d_in[2];
    const float* h0   = (const float*)d_in[3];
    const float* c0   = (const float*)d_in[4];
    const float* Wctx = (const float*)d_in[5];
    const float* bctx = (const float*)d_in[6];
    const float* Wh2a = (const float*)d_in[7];
    const float* bh2a = (const float*)d_in[8];
    const float* Wal  = (const float*)d_in[9];
    const float* bal  = (const float*)d_in[10];
    const float* Wih  = (const float*)d_in[11];
    const float* Whh  = (const float*)d_in[12];
    float* out = (float*)d_out;

    static int attr_set = 0;
    if (!attr_set) {
        cudaFuncSetAttribute(k2_scores, cudaFuncAttributeMaxDynamicSharedMemorySize, K2_SMEM);
        cudaFuncSetAttribute(k5_gates,  cudaFuncAttributeMaxDynamicSharedMemorySize, K5_SMEM);
        attr_set = 1;
    }

    k0_prep<<<4096, 256>>>(Wctx, xt, h0);
    k1_atth<<<dim3(16, 32), dim3(16, 16)>>>(h0, Wh2a, bh2a);
    k_nop<<<1, 32>>>();
    k2_scores<<<dim3(4, Mq / 128), 256, K2_SMEM>>>(att, bctx, Wal);   // capture slot 3
    k3_softmax<<<Bq, 256>>>(bal);
    k0b_wg<<<6144, 256>>>(Wih, Whh);
    k4_attres<<<dim3(2, Bq), 256>>>(att);
    k5_gates<<<dim3(2, 16, 3), 256, K5_SMEM>>>();
    k6_lstm<<<(Bq * RSq + 255) / 256, 256>>>(c0, out, out_size);
}

// round 13
// speedup vs baseline: 1.2081x; 1.0596x over previous
#include <cuda_runtime.h>
#include <cuda_bf16.h>
#include <stdint.h>
#include <stddef.h>

#define Bq  256
#define Lq  196
#define AFq 2048
#define RSq 512
#define AHq 512
#define IEq 512
#define Mq  (Bq * Lq)            // 50176
#define XK  (IEq + AFq + RSq)    // 3072
#define GSEG (Bq * 4 * RSq)      // 524288 (one split-K partial)

// ---------------- device scratch (no allocations allowed) ----------------
__device__ __align__(16) float         g_att_h[Bq * AHq];
__device__ __align__(16) __nv_bfloat16 g_Wctx[AHq * AFq];
__device__ __align__(16) float         g_part[4 * Mq];       // per-nblock partial scores
__device__ __align__(16) float         g_weight[Bq * Lq];
__device__ __align__(16) float         g_x[Bq * XK];          // [xt | att_res | h0] (tf32-rounded)
__device__ __align__(16) float         g_Wg[4 * RSq * XK];    // [Wih | Whh] concat, tf32-rounded
__device__ __align__(16) float         g_gpart[3 * GSEG];     // split-K gate partials

// ---------------- helpers ----------------
__device__ __forceinline__ uint32_t packbf(float lo, float hi) {
    __nv_bfloat162 h = __floats2bfloat162_rn(lo, hi);
    return *reinterpret_cast<uint32_t*>(&h);
}
__device__ __forceinline__ uint32_t f2tf32(float f) {
    uint32_t r; asm("cvt.rna.tf32.f32 %0, %1;" : "=r"(r) : "f"(f)); return r;
}
__device__ __forceinline__ void mma_bf16(float c[4], const uint32_t a[4], const uint32_t b[2]) {
    asm volatile("mma.sync.aligned.m16n8k16.row.col.f32.bf16.bf16.f32 "
        "{%0,%1,%2,%3}, {%4,%5,%6,%7}, {%8,%9}, {%0,%1,%2,%3};"
        : "+f"(c[0]), "+f"(c[1]), "+f"(c[2]), "+f"(c[3])
        : "r"(a[0]), "r"(a[1]), "r"(a[2]), "r"(a[3]), "r"(b[0]), "r"(b[1]));
}
__device__ __forceinline__ void mma_tf32(float c[4], const uint32_t a[4], const uint32_t b[2]) {
    asm volatile("mma.sync.aligned.m16n8k8.row.col.f32.tf32.tf32.f32 "
        "{%0,%1,%2,%3}, {%4,%5,%6,%7}, {%8,%9}, {%0,%1,%2,%3};"
        : "+f"(c[0]), "+f"(c[1]), "+f"(c[2]), "+f"(c[3])
        : "r"(a[0]), "r"(a[1]), "r"(a[2]), "r"(a[3]), "r"(b[0]), "r"(b[1]));
}
__device__ __forceinline__ uint32_t smem_u32(const void* p) {
    return (uint32_t)__cvta_generic_to_shared(p);
}
__device__ __forceinline__ void cp_async16(uint32_t dst, const void* src) {
    asm volatile("cp.async.cg.shared.global [%0], [%1], 16;" :: "r"(dst), "l"(src));
}
__device__ __forceinline__ void cp_commit() {
    asm volatile("cp.async.commit_group;" ::: "memory");
}
__device__ __forceinline__ void cp_wait1() {
    asm volatile("cp.async.wait_group 1;" ::: "memory");
}
__device__ __forceinline__ void ldsm_x4(uint32_t& r0, uint32_t& r1, uint32_t& r2, uint32_t& r3,
                                        uint32_t addr) {
    asm volatile("ldmatrix.sync.aligned.m8n8.x4.shared.b16 {%0,%1,%2,%3}, [%4];"
        : "=r"(r0), "=r"(r1), "=r"(r2), "=r"(r3) : "r"(addr));
}

// ---------------- K0: W_ctx->bf16; xt,h0 -> g_x (tf32-rounded) ----------------
__global__ void k0_prep(const float* __restrict__ Wctx, const float* __restrict__ xt,
                        const float* __restrict__ h0) {
    int i = blockIdx.x * blockDim.x + threadIdx.x;
    if (i < AHq * AFq) g_Wctx[i] = __float2bfloat16(Wctx[i]);
    if (i < Bq * IEq) {
        int b = i >> 9, c = i & 511;
        g_x[(size_t)b * XK + c] = __uint_as_float(f2tf32(xt[i]));
    }
    if (i < Bq * RSq) {
        int b = i >> 9, c = i & 511;
        g_x[(size_t)b * XK + IEq + AFq + c] = __uint_as_float(f2tf32(h0[i]));
    }
}

// ---------------- K0b: g_Wg = [Wih | Whh] tf32-rounded ----------------
__global__ void k0b_wg(const float* __restrict__ Wih, const float* __restrict__ Whh) {
    int i = blockIdx.x * blockDim.x + threadIdx.x;
    if (i >= 4 * RSq * (XK / 4)) return;
    int n = i / (XK / 4), kq = i % (XK / 4);
    float4 v;
    if (kq < 640) v = *(const float4*)(Wih + (size_t)n * 2560 + kq * 4);
    else          v = *(const float4*)(Whh + (size_t)n * 512 + (kq - 640) * 4);
    uint4 o = make_uint4(f2tf32(v.x), f2tf32(v.y), f2tf32(v.z), f2tf32(v.w));
    ((uint4*)g_Wg)[(size_t)n * (XK / 4) + kq] = o;
}

// ---------------- K1: att_h = h0 @ W_h2a^T + b_h2a ----------------
__global__ void k1_atth(const float* __restrict__ h0, const float* __restrict__ W,
                        const float* __restrict__ bias) {
    __shared__ float As[16][16];
    __shared__ float Bs[16][17];
    int tx = threadIdx.x, ty = threadIdx.y;
    int b  = blockIdx.x * 16 + ty;
    int j  = blockIdx.y * 16 + tx;
    float acc = 0.f;
    for (int k0 = 0; k0 < RSq; k0 += 16) {
        As[ty][tx] = h0[b * RSq + k0 + tx];
        Bs[ty][tx] = W[(blockIdx.y * 16 + ty) * RSq + k0 + tx];
        __syncthreads();
        #pragma unroll
        for (int kk = 0; kk < 16; kk++) acc += As[ty][kk] * Bs[tx][kk];
        __syncthreads();
    }
    g_att_h[b * AHq + j] = acc + bias[j];
}

// ---------------- nop: keeps k2 at ncu capture slot ----------------
__global__ void k_nop() {}

// ---------------- K2: fused scores — 3-stage cp.async, 4m x 2n warps (32x64 warp tile) ----------------
// Grid (4, 392): nb fastest (A L2 reuse). Block 256 = 8 warps. Tile 128x128xk32.
#define AROW 160                 // f32 A tile row stride bytes
#define A_STG (128 * AROW)       // 20480
#define BROW 80                  // bf16 B tile row stride
#define B_STG (128 * BROW)       // 10240
#define OFF_B   (3 * A_STG)                 // 61440
#define OFF_ADD (OFF_B + 3 * B_STG)         // 92160
#define OFF_WAL (OFF_ADD + 2 * 128 * 4)     // 93184
#define OFF_RED (OFF_WAL + 128 * 4)         // 93696
#define K2_SMEM (OFF_RED + 128 * 2 * 4)     // 94720
#define NKT2 (AFq / 32)          // 64

__global__ void __launch_bounds__(256, 2)
k2_scores(const float* __restrict__ att, const float* __restrict__ bctx,
          const float* __restrict__ Wal) {
    extern __shared__ __align__(16) char sm[];
    uint32_t smb = smem_u32(sm);
    float* s_add = (float*)(sm + OFF_ADD);   // [2][128]
    float* s_wal = (float*)(sm + OFF_WAL);   // [128]
    float* s_red = (float*)(sm + OFF_RED);   // [128][2]

    int tid = threadIdx.x;
    int warp = tid >> 5, lane = tid & 31;
    int g = lane >> 2, t = lane & 3;
    int wm = warp >> 1, wn = warp & 1;          // 4m x 2n, warp tile 32x64
    int nb    = blockIdx.x;                      // 0..3 (fast dim -> L2 A sharing)
    int mbase = blockIdx.y * 128;
    int nbase = nb * 128;
    int b0 = mbase / Lq;

    {
        int j = tid >> 7, nc = tid & 127;
        int bb = b0 + j; if (bb >= Bq) bb = Bq - 1;
        s_add[j * 128 + nc] = bctx[nbase + nc] + g_att_h[(size_t)bb * AHq + nbase + nc];
        if (tid < 128) s_wal[tid] = Wal[nbase + tid];
    }

    float acc[2][8][4];
    #pragma unroll
    for (int a = 0; a < 2; a++)
        #pragma unroll
        for (int b = 0; b < 8; b++)
            #pragma unroll
            for (int c = 0; c < 4; c++) acc[a][b][c] = 0.f;

    // stage loaders: A fp32 (4 x 16B per thread), B bf16 (2 x 16B per thread)
    auto issue_stage = [&](int kt, int s) {
        int k0 = kt * 32;
        uint32_t aDst = smb + s * A_STG;
        #pragma unroll
        for (int q = 0; q < 4; q++) {
            int idx = q * 256 + tid;
            int row = idx >> 3, seg = idx & 7;
            cp_async16(aDst + row * AROW + seg * 16,
                       att + (size_t)(mbase + row) * AFq + k0 + seg * 4);
        }
        uint32_t bDst = smb + OFF_B + s * B_STG;
        #pragma unroll
        for (int q = 0; q < 2; q++) {
            int idx = q * 256 + tid;
            int row = idx >> 2, c = idx & 3;
            cp_async16(bDst + row * BROW + c * 16,
                       g_Wctx + (size_t)(nbase + row) * AFq + k0 + c * 8);
        }
    };

    // B ldmatrix address: covers 64 cols per warp (4 x ldsm_x4 per k16)
    uint32_t b_off = (uint32_t)(wn * 64 + ((lane >> 4) & 1) * 8 + (lane & 7)) * BROW +
                     ((lane >> 3) & 1) * 16;
    // A LDS base: row = wm*32 + mf*16 + g, col = k16*16 + 2t (f32)
    uint32_t a_off = (uint32_t)(wm * 32 + g) * AROW + t * 8;

    // prologue: stages 0,1
    issue_stage(0, 0); cp_commit();
    issue_stage(1, 1); cp_commit();

    for (int kt = 0; kt < NKT2; kt++) {
        int s = kt % 3;
        cp_wait1();
        __syncthreads();
        if (kt + 2 < NKT2) issue_stage(kt + 2, (kt + 2) % 3);
        cp_commit();

        uint32_t aBase = smb + s * A_STG + a_off;
        uint32_t bBase = smb + OFF_B + s * B_STG + b_off;
        #pragma unroll
        for (int k16 = 0; k16 < 2; k16++) {
            uint32_t bfr[8][2];
            #pragma unroll
            for (int p = 0; p < 4; p++)
                ldsm_x4(bfr[2 * p][0], bfr[2 * p][1], bfr[2 * p + 1][0], bfr[2 * p + 1][1],
                        bBase + (uint32_t)p * 16 * BROW + k16 * 32);
            #pragma unroll
            for (int mf = 0; mf < 2; mf++) {
                uint32_t ab = aBase + (uint32_t)mf * 16 * AROW + k16 * 64;
                float2 v00 = *(const float2*)(sm + (ab - smb));
                float2 v10 = *(const float2*)(sm + (ab - smb) + 8 * AROW);
                float2 v01 = *(const float2*)(sm + (ab - smb) + 32);
                float2 v11 = *(const float2*)(sm + (ab - smb) + 8 * AROW + 32);
                uint32_t afr[4] = { packbf(v00.x, v00.y), packbf(v10.x, v10.y),
                                    packbf(v01.x, v01.y), packbf(v11.x, v11.y) };
                #pragma unroll
                for (int nf = 0; nf < 8; nf++)
                    mma_bf16(acc[mf][nf], afr, bfr[nf]);
            }
        }
        // no trailing barrier: top-of-iter barrier + 3-stage distance cover WAR hazards
    }

    // epilogue: partial score over this block's 128 columns (each warp: 64 cols)
    float rs[2][2];
    #pragma unroll
    for (int mf = 0; mf < 2; mf++) {
        #pragma unroll
        for (int hh = 0; hh < 2; hh++) {
            int row_l = wm * 32 + mf * 16 + hh * 8 + g;
            int m = mbase + row_l;
            int jb = (m / Lq) - b0; if (jb > 1) jb = 1;
            const float* addp = s_add + jb * 128;
            float s = 0.f;
            #pragma unroll
            for (int nf = 0; nf < 8; nf++) {
                #pragma unroll
                for (int ci = 0; ci < 2; ci++) {
                    int nc = wn * 64 + nf * 8 + 2 * t + ci;
                    float v = acc[mf][nf][hh * 2 + ci] + addp[nc];
                    s += s_wal[nc] * tanhf(v);
                }
            }
            rs[mf][hh] = s;
        }
    }
    #pragma unroll
    for (int off = 1; off < 4; off <<= 1)
        #pragma unroll
        for (int mf = 0; mf < 2; mf++)
            #pragma unroll
            for (int hh = 0; hh < 2; hh++)
                rs[mf][hh] += __shfl_xor_sync(0xffffffffu, rs[mf][hh], off);
    __syncthreads();   // all warps done with stage smem + s_add before s_red reuse pattern
    if (t == 0) {
        #pragma unroll
        for (int mf = 0; mf < 2; mf++)
            #pragma unroll
            for (int hh = 0; hh < 2; hh++)
                s_red[(wm * 32 + mf * 16 + hh * 8 + g) * 2 + wn] = rs[mf][hh];
    }
    __syncthreads();
    if (tid < 128) {
        float s = s_red[tid * 2] + s_red[tid * 2 + 1];
        g_part[(size_t)nb * Mq + mbase + tid] = s;
    }
}

// ---------------- K3: sum 4 partials + softmax over L=196 ----------------
__global__ void k3_softmax(const float* __restrict__ bal) {
    int b = blockIdx.x;
    int tid = threadIdx.x;
    __shared__ float sh[256];
    float v = -1e30f;
    if (tid < Lq) {
        int m = b * Lq + tid;
        v = g_part[m] + g_part[Mq + m] + g_part[2 * Mq + m] + g_part[3 * Mq + m] + bal[0];
    }
    sh[tid] = v; __syncthreads();
    for (int s = 128; s > 0; s >>= 1) {
        if (tid < s) sh[tid] = fmaxf(sh[tid], sh[tid + s]);
        __syncthreads();
    }
    float mx = sh[0]; __syncthreads();
    float e = (tid < Lq) ? __expf(v - mx) : 0.f;
    sh[tid] = e; __syncthreads();
    for (int s = 128; s > 0; s >>= 1) {
        if (tid < s) sh[tid] += sh[tid + s];
        __syncthreads();
    }
    float inv = 1.f / sh[0];
    if (tid < Lq) g_weight[b * Lq + tid] = e * inv;
}

// ---------------- K4: att_res = weight @ att_feats (tf32-rounded into g_x) ----------------
__global__ void k4_attres(const float* __restrict__ att) {
    int b  = blockIdx.y;
    int a0 = blockIdx.x * 1024 + threadIdx.x * 4;
    __shared__ float w[Lq];
    for (int i = threadIdx.x; i < Lq; i += blockDim.x) w[i] = g_weight[b * Lq + i];
    __syncthreads();
    float4 acc = make_float4(0.f, 0.f, 0.f, 0.f);
    const float* base = att + (size_t)b * Lq * AFq + a0;
    #pragma unroll 4
    for (int l = 0; l < Lq; l++) {
        float4 v = *(const float4*)(base + (size_t)l * AFq);
        float wl = w[l];
        acc.x += wl * v.x; acc.y += wl * v.y; acc.z += wl * v.z; acc.w += wl * v.w;
    }
    acc.x = __uint_as_float(f2tf32(acc.x));
    acc.y = __uint_as_float(f2tf32(acc.y));
    acc.z = __uint_as_float(f2tf32(acc.z));
    acc.w = __uint_as_float(f2tf32(acc.w));
    *(float4*)(g_x + (size_t)b * XK + IEq + a0) = acc;
}

// ---------------- K5: gate GEMM, tf32, cp.async tiled, split-K=3 ----------------
#define R5 144
#define S5 (128 * R5)
#define K5_SMEM (6 * S5)
__global__ void __launch_bounds__(256, 1)
k5_gates() {
    extern __shared__ __align__(16) char sm5[];
    uint32_t smb = smem_u32(sm5);
    int tid = threadIdx.x;
    int warp = tid >> 5, lane = tid & 31;
    int g = lane >> 2, t = lane & 3;
    int wm = warp >> 2, wn = warp & 3;
    int mbase = blockIdx.x * 128;
    int nbase = blockIdx.y * 128;
    int kb    = blockIdx.z * 1024;

    float acc[4][4][4];
    #pragma unroll
    for (int a = 0; a < 4; a++)
        #pragma unroll
        for (int b = 0; b < 4; b++)
            #pragma unroll
            for (int c = 0; c < 4; c++) acc[a][b][c] = 0.f;

    const float* aP[4]; const float* bP[4]; uint32_t tOff[4];
    #pragma unroll
    for (int q = 0; q < 4; q++) {
        int idx = q * 256 + tid;
        int row = idx >> 3, seg = idx & 7;
        aP[q] = g_x  + (size_t)(mbase + row) * XK + kb + seg * 4;
        bP[q] = g_Wg + (size_t)(nbase + row) * XK + kb + seg * 4;
        tOff[q] = row * R5 + seg * 16;
    }
    auto issue = [&](int kt, int s) {
        int k0 = kt * 32;
        uint32_t aD = smb + s * S5;
        uint32_t bD = smb + 3 * S5 + s * S5;
        #pragma unroll
        for (int q = 0; q < 4; q++) {
            cp_async16(aD + tOff[q], aP[q] + k0);
            cp_async16(bD + tOff[q], bP[q] + k0);
        }
    };

    issue(0, 0); cp_commit();
    issue(1, 1); cp_commit();

    uint32_t aFr = (uint32_t)(wm * 64 + g) * R5 + t * 4;
    uint32_t bFr = (uint32_t)(wn * 32 + g) * R5 + t * 4;

    for (int kt = 0; kt < 32; kt++) {
        int s = kt % 3;
        cp_wait1();
        __syncthreads();
        if (kt < 30) issue(kt + 2, (kt + 2) % 3);
        cp_commit();

        const char* aB = sm5 + s * S5;
        const char* bB = sm5 + 3 * S5 + s * S5;
        #pragma unroll
        for (int ks = 0; ks < 4; ks++) {
            uint32_t kc = ks * 32;
            uint32_t bfr[4][2];
            #pragma unroll
            for (int nf = 0; nf < 4; nf++) {
                bfr[nf][0] = *(const uint32_t*)(bB + bFr + nf * 8 * R5 + kc);
                bfr[nf][1] = *(const uint32_t*)(bB + bFr + nf * 8 * R5 + kc + 16);
            }
            #pragma unroll
            for (int mf = 0; mf < 4; mf++) {
                uint32_t afr[4];
                afr[0] = *(const uint32_t*)(aB + aFr + mf * 16 * R5 + kc);
                afr[1] = *(const uint32_t*)(aB + aFr + (mf * 16 + 8) * R5 + kc);
                afr[2] = *(const uint32_t*)(aB + aFr + mf * 16 * R5 + kc + 16);
                afr[3] = *(const uint32_t*)(aB + aFr + (mf * 16 + 8) * R5 + kc + 16);
                #pragma unroll
                for (int nf = 0; nf < 4; nf++)
                    mma_tf32(acc[mf][nf], afr, bfr[nf]);
            }
        }
    }

    float* outp = g_gpart + (size_t)blockIdx.z * GSEG;
    #pragma unroll
    for (int mf = 0; mf < 4; mf++)
        #pragma unroll
        for (int nf = 0; nf < 4; nf++)
            #pragma unroll
            for (int idx = 0; idx < 4; idx++) {
                int hh = idx >> 1, ci = idx & 1;
                int row = mbase + wm * 64 + mf * 16 + hh * 8 + g;
                int col = nbase + wn * 32 + nf * 8 + 2 * t + ci;
                outp[(size_t)row * 2048 + col] = acc[mf][nf][idx];
            }
}

// ---------------- K6: sum split-K partials + LSTM pointwise + output ----------------
__global__ void k6_lstm(const float* __restrict__ c0, float* __restrict__ out, int out_size) {
    int i = blockIdx.x * blockDim.x + threadIdx.x;
    if (i >= Bq * RSq) return;
    int b = i >> 9, r = i & 511;
    size_t base = (size_t)b * 2048;
    auto gv = [&](int col) {
        size_t idx = base + col;
        return g_gpart[idx] + g_gpart[GSEG + idx] + g_gpart[2 * (size_t)GSEG + idx];
    };
    float gi = 1.f / (1.f + __expf(-gv(r)));
    float gf = 1.f / (1.f + __expf(-gv(512 + r)));
    float gg = tanhf(gv(1024 + r));
    float go = 1.f / (1.f + __expf(-gv(1536 + r)));
    float c = gf * c0[i] + gi * gg;
    float h = go * tanhf(c);
    const int N = Bq * RSq;
    out[i] = h;
    if (out_size >= 3 * N) { out[N + i] = h; out[2 * N + i] = c; }
    else if (out_size >= 2 * N) { out[N + i] = c; }
}

// ---------------- launch ----------------
extern "C" void kernel_launch(void* const* d_in, const int* in_sizes, int n_in,
                              void* d_out, int out_size) {
    const float* xt   = (const float*)d_in[0];
    const float* att  = (const float*)d_in[2];
    const float* h0   = (const float*)d_in[3];
    const float* c0   = (const float*)d_in[4];
    const float* Wctx = (const float*)d_in[5];
    const float* bctx = (const float*)d_in[6];
    const float* Wh2a = (const float*)d_in[7];
    const float* bh2a = (const float*)d_in[8];
    const float* Wal  = (const float*)d_in[9];
    const float* bal  = (const float*)d_in[10];
    const float* Wih  = (const float*)d_in[11];
    const float* Whh  = (const float*)d_in[12];
    float* out = (float*)d_out;

    static int attr_set = 0;
    if (!attr_set) {
        cudaFuncSetAttribute(k2_scores, cudaFuncAttributeMaxDynamicSharedMemorySize, K2_SMEM);
        cudaFuncSetAttribute(k5_gates,  cudaFuncAttributeMaxDynamicSharedMemorySize, K5_SMEM);
        attr_set = 1;
    }

    k0_prep<<<4096, 256>>>(Wctx, xt, h0);
    k1_atth<<<dim3(16, 32), dim3(16, 16)>>>(h0, Wh2a, bh2a);
    k_nop<<<1, 32>>>();
    k2_scores<<<dim3(4, Mq / 128), 256, K2_SMEM>>>(att, bctx, Wal);   // capture slot 3
    k3_softmax<<<Bq, 256>>>(bal);
    k0b_wg<<<6144, 256>>>(Wih, Whh);
    k4_attres<<<dim3(2, Bq), 256>>>(att);
    k5_gates<<<dim3(2, 16, 3), 256, K5_SMEM>>>();
    k6_lstm<<<(Bq * RSq + 255) / 256, 256>>>(c0, out, out_size);
}